// round 2
// baseline (speedup 1.0000x reference)
#include <cuda_runtime.h>
#include <cuda_fp16.h>

#define D 64
#define ALPHA 0.2f
#define MAX_N 131072
#define MAX_E 2200000

// Scratch (static device globals — zero-initialized at load; every kernel
// sequence below restores g_cnt to zero so graph replays are self-consistent)
__device__ int     g_cnt[MAX_N];
__device__ int     g_rowptr[MAX_N + 1];
__device__ int     g_blocksum[512];
__device__ int     g_col[MAX_E];
__device__ int     g_slot[MAX_E];           // per-edge within-row slot from hist
__device__ float2  g_s1[MAX_N];             // per-node source-side scores (h0,h1)
__device__ float2  g_s2[MAX_N];             // per-node dest-side scores (h0,h1)
__device__ __half2 g_xh[MAX_N * 32];        // fp16 copy of x, 2 elems per lane

// Histogram + slot assignment. Requires g_cnt == 0 on entry (true at module
// load and re-established by k_scan3 each run).
__global__ void k_hist(const int* __restrict__ row, int E) {
    int i = blockIdx.x * blockDim.x + threadIdx.x;
    if (i < E) g_slot[i] = atomicAdd(&g_cnt[row[i]], 1);
}

// One warp per node: per-head scores + fp16 conversion of x (x read once).
__global__ void k_precompute(const float* __restrict__ x,
                             const float* __restrict__ W,
                             const float* __restrict__ a, int n) {
    int warp = (blockIdx.x * blockDim.x + threadIdx.x) >> 5;
    int lane = threadIdx.x & 31;
    if (warp >= n) return;
    float2 xv = reinterpret_cast<const float2*>(x)[warp * 32 + lane];
    g_xh[warp * 32 + lane] = __floats2half2_rn(xv.x, xv.y);
    int l2 = lane * 2;
    float h00 = xv.x * W[l2],      h01 = xv.y * W[l2 + 1];
    float h10 = xv.x * W[64 + l2], h11 = xv.y * W[64 + l2 + 1];
    float s10 = h00 * a[l2]       + h01 * a[l2 + 1];
    float s20 = h00 * a[64 + l2]  + h01 * a[64 + l2 + 1];
    float s11 = h10 * a[128 + l2] + h11 * a[128 + l2 + 1];
    float s21 = h10 * a[192 + l2] + h11 * a[192 + l2 + 1];
    #pragma unroll
    for (int o = 16; o; o >>= 1) {
        s10 += __shfl_xor_sync(0xffffffffu, s10, o);
        s20 += __shfl_xor_sync(0xffffffffu, s20, o);
        s11 += __shfl_xor_sync(0xffffffffu, s11, o);
        s21 += __shfl_xor_sync(0xffffffffu, s21, o);
    }
    if (lane == 0) {
        g_s1[warp] = make_float2(s10, s11);
        g_s2[warp] = make_float2(s20, s21);
    }
}

// 3-kernel exclusive scan of g_cnt -> g_rowptr
__global__ void k_scan1(int n) {
    __shared__ int sh[512];
    int t = threadIdx.x;
    int i = blockIdx.x * 512 + t;
    int v = (i < n) ? g_cnt[i] : 0;
    sh[t] = v;
    __syncthreads();
    #pragma unroll
    for (int o = 1; o < 512; o <<= 1) {
        int tmp = (t >= o) ? sh[t - o] : 0;
        __syncthreads();
        sh[t] += tmp;
        __syncthreads();
    }
    if (i < n) g_rowptr[i] = sh[t] - v;   // local exclusive
    if (t == 511) g_blocksum[blockIdx.x] = sh[511];
}

__global__ void k_scan2(int nb) {
    __shared__ int sh[512];
    int t = threadIdx.x;
    int v = (t < nb) ? g_blocksum[t] : 0;
    sh[t] = v;
    __syncthreads();
    #pragma unroll
    for (int o = 1; o < 512; o <<= 1) {
        int tmp = (t >= o) ? sh[t - o] : 0;
        __syncthreads();
        sh[t] += tmp;
        __syncthreads();
    }
    if (t < nb) g_blocksum[t] = sh[t] - v;  // exclusive block bases
}

// Adds block bases; also re-zeroes g_cnt (restores invariant for next replay)
__global__ void k_scan3(int n, int E) {
    int i = blockIdx.x * 512 + threadIdx.x;
    if (i < n) {
        g_rowptr[i] += g_blocksum[blockIdx.x];
        g_cnt[i] = 0;
    }
    if (i == n) g_rowptr[n] = E;
}

// Edge-parallel CSR fill: no atomics (slot precomputed by hist), 4B write.
__global__ void k_scatter(const int* __restrict__ row,
                          const int* __restrict__ col, int E) {
    int i = blockIdx.x * blockDim.x + threadIdx.x;
    if (i >= E) return;
    g_col[g_rowptr[row[i]] + g_slot[i]] = col[i];
}

// One warp per node. Batch: each lane loads one edge's col (coalesced),
// gathers s2 and computes both head weights, then the warp shuffles
// (col, w0, w1) out per edge and all lanes gather the fp16 x row.
__global__ void k_aggregate(float* __restrict__ out, int n) {
    int warp = (blockIdx.x * blockDim.x + threadIdx.x) >> 5;
    int lane = threadIdx.x & 31;
    if (warp >= n) return;
    int beg = g_rowptr[warp];
    int end = g_rowptr[warp + 1];
    float2 s1 = g_s1[warp];
    float a00 = 0.f, a01 = 0.f, a10 = 0.f, a11 = 0.f;
    float rs0 = 0.f, rs1 = 0.f;
    for (int base = beg; base < end; base += 32) {
        int e = base + lane;
        int c = 0;
        float w0 = 0.f, w1 = 0.f;
        if (e < end) {
            c = g_col[e];
            float2 s2 = g_s2[c];
            float sc0 = s1.x + s2.x;
            float sc1 = s1.y + s2.y;
            w0 = __expf(sc0 > 0.f ? sc0 : ALPHA * sc0);
            w1 = __expf(sc1 > 0.f ? sc1 : ALPHA * sc1);
        }
        int m = min(32, end - base);
        #pragma unroll 4
        for (int j = 0; j < m; j++) {
            int   cc  = __shfl_sync(0xffffffffu, c,  j);
            float ww0 = __shfl_sync(0xffffffffu, w0, j);
            float ww1 = __shfl_sync(0xffffffffu, w1, j);
            float2 xf = __half22float2(g_xh[cc * 32 + lane]);
            a00 += ww0 * xf.x; a01 += ww0 * xf.y;
            a10 += ww1 * xf.x; a11 += ww1 * xf.y;
            rs0 += ww0; rs1 += ww1;
        }
    }
    float i0 = 0.5f / rs0, i1 = 0.5f / rs1;
    float2 o;
    o.x = a00 * i0 + a10 * i1;
    o.y = a01 * i0 + a11 * i1;
    reinterpret_cast<float2*>(out)[warp * 32 + lane] = o;
}

extern "C" void kernel_launch(void* const* d_in, const int* in_sizes, int n_in,
                              void* d_out, int out_size) {
    const float* x  = (const float*)d_in[0];
    const int*   ei = (const int*)d_in[1];
    const float* W  = (const float*)d_in[2];
    const float* a  = (const float*)d_in[3];
    float* out = (float*)d_out;

    int n = in_sizes[0] / D;
    int E = in_sizes[1] / 2;
    const int* row = ei;
    const int* col = ei + E;

    const int T = 256;
    int nbE = (E + T - 1) / T;
    int nbW = (n * 32 + T - 1) / T;      // one warp per node
    int nbS = (n + 511) / 512;

    k_hist<<<nbE, T>>>(row, E);
    k_precompute<<<nbW, T>>>(x, W, a, n);
    k_scan1<<<nbS, 512>>>(n);
    k_scan2<<<1, 512>>>(nbS);
    k_scan3<<<(n + 512) / 512, 512>>>(n, E);
    k_scatter<<<nbE, T>>>(row, col, E);
    k_aggregate<<<nbW, T>>>(out, n);
}